// round 1
// baseline (speedup 1.0000x reference)
#include <cuda_runtime.h>
#include <math.h>

// ---------------- problem constants ----------------
#define T_SEQ 2048
#define DIM   2048
#define NH    16
#define NOPE  128
#define ROPED 64
#define VD    128
#define QKD   (NOPE + ROPED)        // 192
#define QLORA 768
#define KVLORA 512
#define KVAW  (KVLORA + ROPED)      // 576

// ---------------- scratch (static device globals; no allocs) ----------------
__device__ float g_qa    [T_SEQ * QLORA];            // x @ wq_a^T   (rmsnorm in-place)
__device__ float g_kvfull[T_SEQ * KVAW];             // x @ wkv_a^T
__device__ float g_kvnorm[T_SEQ * KVLORA];           // rmsnorm(c_kv)
__device__ float g_q     [T_SEQ * NH * QKD];         // q (rope applied in-place)
__device__ float g_kv    [T_SEQ * NH * (NOPE + VD)]; // kv = kvnorm @ wkv_b^T
__device__ float g_kpe   [T_SEQ * ROPED];            // roped k_pe
__device__ float g_kh    [T_SEQ * NH * QKD];         // concat(k_nope, k_pe bcast)
__device__ float g_scores[(long long)NH * T_SEQ * T_SEQ]; // 256 MB score/prob matrix
__device__ float g_y     [T_SEQ * NH * VD];          // attention output

// ---------------- generic tiled SGEMM ----------------
// C[M,N] = A[M,K] * op(B);  TRANSB: B is [N,K] (C=A*B^T), else B is [K,N].
// CAUSAL: 0 = none; 1 = skip blocks strictly above diagonal (for S=QK^T);
//         2 = limit K-loop to m0+BM (for Y=P*V with P zeroed above diagonal).
template<bool TRANSB, int CAUSAL>
__global__ void sgemm_kernel(const float* __restrict__ A,
                             const float* __restrict__ B,
                             float* __restrict__ C,
                             int M, int N, int K,
                             int lda, int ldb, int ldc,
                             long long strideA, long long strideB, long long strideC)
{
    constexpr int BM = 128, BN = 128, BK = 8;
    __shared__ float As[BK][BM];
    __shared__ float Bs[BK][BN];

    const int bz = blockIdx.z;
    A += bz * strideA;
    B += bz * strideB;
    C += bz * strideC;

    const int m0 = blockIdx.y * BM;
    const int n0 = blockIdx.x * BN;
    if (CAUSAL == 1 && n0 > m0) return;          // whole tile masked
    const int kEnd = (CAUSAL == 2) ? min(K, m0 + BM) : K;

    const int tid = threadIdx.x;
    const int tx = tid & 15;        // 0..15 (col group)
    const int ty = tid >> 4;        // 0..15 (row group)

    // A-tile load: thread -> (row = tid/2, 4 consecutive k)
    const int arow = tid >> 1;
    const int akq  = (tid & 1) * 4;
    // B-tile load (NN): thread -> (k = tid/32, 4 consecutive n)
    const int bk = tid >> 5;
    const int bn = (tid & 31) * 4;

    float acc[8][8];
    #pragma unroll
    for (int i = 0; i < 8; i++)
        #pragma unroll
        for (int j = 0; j < 8; j++) acc[i][j] = 0.f;

    for (int k0 = 0; k0 < kEnd; k0 += BK) {
        // ---- load A tile (M multiple of 128, K multiple of 8: no guards) ----
        float4 a4 = *(const float4*)(A + (long long)(m0 + arow) * lda + k0 + akq);
        As[akq + 0][arow] = a4.x;
        As[akq + 1][arow] = a4.y;
        As[akq + 2][arow] = a4.z;
        As[akq + 3][arow] = a4.w;

        // ---- load B tile ----
        if (TRANSB) {
            float4 b4 = make_float4(0.f, 0.f, 0.f, 0.f);
            if (n0 + arow < N)
                b4 = *(const float4*)(B + (long long)(n0 + arow) * ldb + k0 + akq);
            Bs[akq + 0][arow] = b4.x;
            Bs[akq + 1][arow] = b4.y;
            Bs[akq + 2][arow] = b4.z;
            Bs[akq + 3][arow] = b4.w;
        } else {
            float4 b4 = make_float4(0.f, 0.f, 0.f, 0.f);
            if (n0 + bn < N)
                b4 = *(const float4*)(B + (long long)(k0 + bk) * ldb + n0 + bn);
            *(float4*)&Bs[bk][bn] = b4;
        }
        __syncthreads();

        #pragma unroll
        for (int k = 0; k < BK; k++) {
            float a[8], b[8];
            *(float4*)(a)     = *(const float4*)&As[k][ty * 8];
            *(float4*)(a + 4) = *(const float4*)&As[k][ty * 8 + 4];
            *(float4*)(b)     = *(const float4*)&Bs[k][tx * 8];
            *(float4*)(b + 4) = *(const float4*)&Bs[k][tx * 8 + 4];
            #pragma unroll
            for (int i = 0; i < 8; i++)
                #pragma unroll
                for (int j = 0; j < 8; j++)
                    acc[i][j] += a[i] * b[j];
        }
        __syncthreads();
    }

    // ---- store C (guard N; N always multiple of 4) ----
    #pragma unroll
    for (int i = 0; i < 8; i++) {
        const int m = m0 + ty * 8 + i;
        #pragma unroll
        for (int j = 0; j < 8; j += 4) {
            const int n = n0 + tx * 8 + j;
            if (n < N) {
                *(float4*)(C + (long long)m * ldc + n) =
                    make_float4(acc[i][j], acc[i][j + 1], acc[i][j + 2], acc[i][j + 3]);
            }
        }
    }
}

// ---------------- RMSNorm (one block per row) ----------------
__global__ void rmsnorm_kernel(const float* __restrict__ in,
                               const float* __restrict__ w,
                               float* __restrict__ out,
                               int C, int ldin, int ldout)
{
    const int row = blockIdx.x;
    const float* x = in + (long long)row * ldin;
    float* o = out + (long long)row * ldout;
    __shared__ float red[256];

    float s = 0.f;
    for (int c = threadIdx.x; c < C; c += 256) {
        float v = x[c];
        s += v * v;
    }
    red[threadIdx.x] = s;
    __syncthreads();
    for (int st = 128; st > 0; st >>= 1) {
        if (threadIdx.x < st) red[threadIdx.x] += red[threadIdx.x + st];
        __syncthreads();
    }
    const float scale = rsqrtf(red[0] / (float)C + 1e-6f);
    for (int c = threadIdx.x; c < C; c += 256)
        o[c] = x[c] * scale * w[c];
}

// ---------------- RoPE on q (in place, last 64 dims of each head) ----------------
__global__ void rope_q_kernel(float* __restrict__ q, const float* __restrict__ freqs)
{
    const int total = T_SEQ * NH * (ROPED / 2);
    int idx = blockIdx.x * blockDim.x + threadIdx.x;
    if (idx >= total) return;
    const int i = idx % (ROPED / 2);
    const int h = (idx / (ROPED / 2)) % NH;
    const int t = idx / (NH * (ROPED / 2));
    const double f = (double)freqs[t * (ROPED / 2) + i];
    const float c = (float)cos(f);
    const float s = (float)sin(f);
    float* p = q + (long long)t * (NH * QKD) + h * QKD + NOPE + 2 * i;
    const float x1 = p[0], x2 = p[1];
    p[0] = x1 * c - x2 * s;
    p[1] = x1 * s + x2 * c;
}

// ---------------- RoPE on k_pe (shared single head) ----------------
__global__ void rope_kpe_kernel(const float* __restrict__ kvfull,
                                const float* __restrict__ freqs,
                                float* __restrict__ kpe)
{
    const int total = T_SEQ * (ROPED / 2);
    int idx = blockIdx.x * blockDim.x + threadIdx.x;
    if (idx >= total) return;
    const int i = idx % (ROPED / 2);
    const int t = idx / (ROPED / 2);
    const double f = (double)freqs[t * (ROPED / 2) + i];
    const float c = (float)cos(f);
    const float s = (float)sin(f);
    const float* p = kvfull + (long long)t * KVAW + KVLORA + 2 * i;
    const float x1 = p[0], x2 = p[1];
    kpe[t * ROPED + 2 * i]     = x1 * c - x2 * s;
    kpe[t * ROPED + 2 * i + 1] = x1 * s + x2 * c;
}

// ---------------- build kh = concat(k_nope, broadcast k_pe) ----------------
__global__ void build_kh_kernel(const float* __restrict__ kv,
                                const float* __restrict__ kpe,
                                float* __restrict__ kh)
{
    const int total = T_SEQ * NH * QKD;
    int idx = blockIdx.x * blockDim.x + threadIdx.x;
    if (idx >= total) return;
    const int d = idx % QKD;
    const int h = (idx / QKD) % NH;
    const int t = idx / (NH * QKD);
    float v;
    if (d < NOPE)
        v = kv[(long long)t * (NH * (NOPE + VD)) + h * (NOPE + VD) + d];
    else
        v = kpe[t * ROPED + (d - NOPE)];
    kh[idx] = v;
}

// ---------------- causal softmax over scores (scale applied here) ----------------
__global__ void softmax_kernel(float* __restrict__ scores)
{
    const int s = blockIdx.x;
    const int h = blockIdx.y;
    float* row = scores + ((long long)h * T_SEQ + s) * T_SEQ;
    const float scale = (float)QKD * -0.5f;   // matches reference literally
    const int n = s + 1;
    __shared__ float red[256];

    float m = -INFINITY;
    for (int t = threadIdx.x; t < n; t += 256)
        m = fmaxf(m, row[t] * scale);
    red[threadIdx.x] = m;
    __syncthreads();
    for (int st = 128; st > 0; st >>= 1) {
        if (threadIdx.x < st) red[threadIdx.x] = fmaxf(red[threadIdx.x], red[threadIdx.x + st]);
        __syncthreads();
    }
    m = red[0];
    __syncthreads();

    float sum = 0.f;
    for (int t = threadIdx.x; t < n; t += 256)
        sum += expf(row[t] * scale - m);
    red[threadIdx.x] = sum;
    __syncthreads();
    for (int st = 128; st > 0; st >>= 1) {
        if (threadIdx.x < st) red[threadIdx.x] += red[threadIdx.x + st];
        __syncthreads();
    }
    const float inv = 1.0f / red[0];

    for (int t = threadIdx.x; t < n; t += 256)
        row[t] = expf(row[t] * scale - m) * inv;

    // zero the masked tail inside this 128-row GEMM block (Y GEMM reads it)
    const int zend = min(T_SEQ, ((s >> 7) + 1) << 7);
    for (int t = n + threadIdx.x; t < zend; t += 256)
        row[t] = 0.f;
}

// ---------------- launch ----------------
extern "C" void kernel_launch(void* const* d_in, const int* in_sizes, int n_in,
                              void* d_out, int out_size)
{
    (void)in_sizes; (void)n_in;
    const float* x        = (const float*)d_in[0];
    const float* freqs    = (const float*)d_in[1];
    // d_in[2] = mask (unused; causality applied analytically)
    const float* wq_a     = (const float*)d_in[3];
    const float* q_norm_w = (const float*)d_in[4];
    const float* wq_b     = (const float*)d_in[5];
    const float* wkv_a    = (const float*)d_in[6];
    const float* kv_norm_w= (const float*)d_in[7];
    const float* wkv_b    = (const float*)d_in[8];
    const float* wo       = (const float*)d_in[9];
    float* out = (float*)d_out;

    float *p_qa, *p_kvfull, *p_kvnorm, *p_q, *p_kv, *p_kpe, *p_kh, *p_scores, *p_y;
    cudaGetSymbolAddress((void**)&p_qa,     g_qa);
    cudaGetSymbolAddress((void**)&p_kvfull, g_kvfull);
    cudaGetSymbolAddress((void**)&p_kvnorm, g_kvnorm);
    cudaGetSymbolAddress((void**)&p_q,      g_q);
    cudaGetSymbolAddress((void**)&p_kv,     g_kv);
    cudaGetSymbolAddress((void**)&p_kpe,    g_kpe);
    cudaGetSymbolAddress((void**)&p_kh,     g_kh);
    cudaGetSymbolAddress((void**)&p_scores, g_scores);
    cudaGetSymbolAddress((void**)&p_y,      g_y);

    const int TPB = 256;

    // 1) q_a = x @ wq_a^T   [2048,768]
    sgemm_kernel<true,0><<<dim3(6,16,1), TPB>>>(x, wq_a, p_qa,
        T_SEQ, QLORA, DIM, DIM, DIM, QLORA, 0, 0, 0);
    // 2) kv_full = x @ wkv_a^T  [2048,576]
    sgemm_kernel<true,0><<<dim3(5,16,1), TPB>>>(x, wkv_a, p_kvfull,
        T_SEQ, KVAW, DIM, DIM, DIM, KVAW, 0, 0, 0);
    // 3) rmsnorm q_a (in place)
    rmsnorm_kernel<<<T_SEQ, TPB>>>(p_qa, q_norm_w, p_qa, QLORA, QLORA, QLORA);
    // 4) rmsnorm c_kv -> kvnorm
    rmsnorm_kernel<<<T_SEQ, TPB>>>(p_kvfull, kv_norm_w, p_kvnorm, KVLORA, KVAW, KVLORA);
    // 5) q = qa_norm @ wq_b^T  [2048,3072]
    sgemm_kernel<true,0><<<dim3(24,16,1), TPB>>>(p_qa, wq_b, p_q,
        T_SEQ, NH*QKD, QLORA, QLORA, QLORA, NH*QKD, 0, 0, 0);
    // 6) kv = kvnorm @ wkv_b^T  [2048,4096]
    sgemm_kernel<true,0><<<dim3(32,16,1), TPB>>>(p_kvnorm, wkv_b, p_kv,
        T_SEQ, NH*(NOPE+VD), KVLORA, KVLORA, KVLORA, NH*(NOPE+VD), 0, 0, 0);
    // 7) rope on q_pe (in place)
    rope_q_kernel<<<(T_SEQ*NH*(ROPED/2) + TPB - 1)/TPB, TPB>>>(p_q, freqs);
    // 8) rope on k_pe
    rope_kpe_kernel<<<(T_SEQ*(ROPED/2) + TPB - 1)/TPB, TPB>>>(p_kvfull, freqs, p_kpe);
    // 9) build kh
    build_kh_kernel<<<(T_SEQ*NH*QKD + TPB - 1)/TPB, TPB>>>(p_kv, p_kpe, p_kh);
    // 10) S_h = Q_h @ K_h^T (batched over heads, skip masked tiles)
    sgemm_kernel<true,1><<<dim3(16,16,NH), TPB>>>(p_q, p_kh, p_scores,
        T_SEQ, T_SEQ, QKD, NH*QKD, NH*QKD, T_SEQ,
        (long long)QKD, (long long)QKD, (long long)T_SEQ*T_SEQ);
    // 11) causal softmax (scale -96 applied here)
    softmax_kernel<<<dim3(T_SEQ, NH), TPB>>>(p_scores);
    // 12) Y_h = P_h @ V_h (batched, causal K-limit)
    sgemm_kernel<false,2><<<dim3(1,16,NH), TPB>>>(p_scores, p_kv + NOPE, p_y,
        T_SEQ, VD, T_SEQ, T_SEQ, NH*(NOPE+VD), NH*VD,
        (long long)T_SEQ*T_SEQ, (long long)(NOPE+VD), (long long)VD);
    // 13) out = y @ wo^T  [2048,2048]
    sgemm_kernel<true,0><<<dim3(16,16,1), TPB>>>(p_y, wo, out,
        T_SEQ, DIM, NH*VD, NH*VD, NH*VD, DIM, 0, 0, 0);
}

// round 8
// speedup vs baseline: 2.4195x; 2.4195x over previous
#include <cuda_runtime.h>
#include <cuda_bf16.h>
#include <cstdint>
#include <math.h>

// ---------------- problem constants ----------------
#define T_SEQ 2048
#define DIM   2048
#define NH    16
#define NOPE  128
#define ROPED 64
#define VD    128
#define QKD   (NOPE + ROPED)        // 192
#define QLORA 768
#define KVLORA 512
#define KVAW  (KVLORA + ROPED)      // 576

typedef __nv_bfloat16 bf16;

// ---------------- scratch (static device globals; no allocs) ----------------
__device__ bf16 g_xh [T_SEQ * DIM],        g_xl [T_SEQ * DIM];
__device__ bf16 g_wqa_h [QLORA * DIM],     g_wqa_l [QLORA * DIM];
__device__ bf16 g_wkva_h[KVAW * DIM],      g_wkva_l[KVAW * DIM];
__device__ bf16 g_wqb_h [NH*QKD * QLORA],  g_wqb_l [NH*QKD * QLORA];
__device__ bf16 g_wkvb_h[NH*(NOPE+VD) * KVLORA], g_wkvb_l[NH*(NOPE+VD) * KVLORA];
__device__ bf16 g_wo_h  [DIM * NH*VD],     g_wo_l  [DIM * NH*VD];

__device__ float g_qa    [T_SEQ * QLORA];
__device__ bf16  g_qan_h [T_SEQ * QLORA],  g_qan_l [T_SEQ * QLORA];
__device__ float g_kvfull[T_SEQ * KVAW];
__device__ bf16  g_kvn_h [T_SEQ * KVLORA], g_kvn_l [T_SEQ * KVLORA];
__device__ float g_q     [T_SEQ * NH * QKD];
__device__ bf16  g_q_h   [T_SEQ * NH * QKD], g_q_l [T_SEQ * NH * QKD];
__device__ float g_kv    [T_SEQ * NH * (NOPE + VD)];
__device__ float g_kpe   [T_SEQ * ROPED];
__device__ bf16  g_kh_h  [T_SEQ * NH * QKD], g_kh_l[T_SEQ * NH * QKD];
__device__ bf16  g_vt_h  [NH * VD * T_SEQ],  g_vt_l[NH * VD * T_SEQ];
__device__ float g_scores[(long long)NH * T_SEQ * T_SEQ];    // 256 MB
__device__ bf16  g_p_h   [(long long)NH * T_SEQ * T_SEQ];    // 128 MB
__device__ bf16  g_p_l   [(long long)NH * T_SEQ * T_SEQ];    // 128 MB
__device__ float g_y     [T_SEQ * NH * VD];
__device__ bf16  g_y_h   [T_SEQ * NH * VD], g_y_l[T_SEQ * NH * VD];

// ---------------- helpers ----------------
__device__ __forceinline__ uint32_t s2u(const void* p) {
    uint32_t a;
    asm("{ .reg .u64 t; cvta.to.shared.u64 t, %1; cvt.u32.u64 %0, t; }" : "=r"(a) : "l"(p));
    return a;
}

#define SWZ(off) ((off) ^ (((off) >> 3) & 0x70))

__device__ __forceinline__ void cpa16(uint32_t dst, const void* src, int sz) {
    asm volatile("cp.async.cg.shared.global [%0], [%1], 16, %2;"
                 :: "r"(dst), "l"(src), "r"(sz) : "memory");
}
__device__ __forceinline__ void cpa_commit_wait() {
    asm volatile("cp.async.commit_group;" ::: "memory");
    asm volatile("cp.async.wait_group 0;" ::: "memory");
}

__device__ __forceinline__ void ldsm4(uint32_t* r, uint32_t addr) {
    asm volatile("ldmatrix.sync.aligned.m8n8.x4.shared.b16 {%0,%1,%2,%3}, [%4];"
                 : "=r"(r[0]), "=r"(r[1]), "=r"(r[2]), "=r"(r[3]) : "r"(addr));
}

__device__ __forceinline__ void mma16816(float* d, const uint32_t* a, const uint32_t* b) {
    asm volatile("mma.sync.aligned.m16n8k16.row.col.f32.bf16.bf16.f32 "
                 "{%0,%1,%2,%3}, {%4,%5,%6,%7}, {%8,%9}, {%0,%1,%2,%3};"
                 : "+f"(d[0]), "+f"(d[1]), "+f"(d[2]), "+f"(d[3])
                 : "r"(a[0]), "r"(a[1]), "r"(a[2]), "r"(a[3]), "r"(b[0]), "r"(b[1]));
}

__device__ __forceinline__ void split2(float v, bf16& h, bf16& l) {
    h = __float2bfloat16(v);
    l = __float2bfloat16(v - __bfloat162float(h));
}

// ---------------- HMMA bf16x3 GEMM ----------------
// C[M,N] fp32 = A[M,K] * B[N,K]^T with A,B as hi/lo bf16 splits (both row-major,
// K contiguous). 128x128 CTA tile, 8 warps (2x4), warp tile 64x32, K chunks of 64.
// CAUSAL: 0 none, 1 skip n0>m0 tiles (S=QK^T), 2 K-limit m0+128 (Y=P V).
static constexpr int GSMEM = 65536;   // 4 tiles of 16 KB (Ah, Al, Bh, Bl)

template<int CAUSAL>
__global__ void __launch_bounds__(256) bfgemm_kernel(
    const bf16* __restrict__ Ah, const bf16* __restrict__ Al,
    const bf16* __restrict__ Bh, const bf16* __restrict__ Bl,
    float* __restrict__ C,
    int M, int N, int K, int lda, int ldb, int ldc,
    long long sA, long long sB, long long sC)
{
    extern __shared__ char smem[];
    const int m0 = blockIdx.y * 128;
    const int n0 = blockIdx.x * 128;
    if (CAUSAL == 1 && n0 > m0) return;
    const int kEnd = (CAUSAL == 2) ? min(K, m0 + 128) : K;

    const long long z = blockIdx.z;
    Ah += z * sA;  Al += z * sA;
    Bh += z * sB;  Bl += z * sB;
    C  += z * sC;

    const int tid = threadIdx.x;
    const int wid = tid >> 5;
    const int lane = tid & 31;
    const int wm = (wid & 1) * 64;     // warp m-offset in tile
    const int wn = (wid >> 1) * 32;    // warp n-offset in tile

    const uint32_t sb = s2u(smem);
    const uint32_t SA_H = 0, SA_L = 16384, SB_H = 32768, SB_L = 49152;

    // loader mapping: 256 threads, each row handled by 2 threads (4x16B each)
    const int lrow = tid >> 1;             // 0..127
    const int lc0  = (tid & 1) * 4;        // 16B-chunk base (0 or 4)

    float acc[4][4][4];
    #pragma unroll
    for (int i = 0; i < 4; i++)
        #pragma unroll
        for (int j = 0; j < 4; j++)
            #pragma unroll
            for (int r = 0; r < 4; r++) acc[i][j][r] = 0.f;

    const int sub = lane >> 3;     // ldmatrix quadrant
    const int l8  = lane & 7;

    for (int k0 = 0; k0 < kEnd; k0 += 64) {
        // ---- stage chunk into smem via cp.async ----
        const bf16* arh = Ah + (long long)(m0 + lrow) * lda + k0;
        const bf16* arl = Al + (long long)(m0 + lrow) * lda + k0;
        const bool bval = (n0 + lrow) < N;
        const long long brow = bval ? (long long)(n0 + lrow) : 0;
        const bf16* brh = Bh + brow * ldb + k0;
        const bf16* brl = Bl + brow * ldb + k0;
        const int bsz = bval ? 16 : 0;
        #pragma unroll
        for (int j = 0; j < 4; j++) {
            const uint32_t so = SWZ(lrow * 128 + (lc0 + j) * 16);
            cpa16(sb + SA_H + so, arh + (lc0 + j) * 8, 16);
            cpa16(sb + SA_L + so, arl + (lc0 + j) * 8, 16);
            cpa16(sb + SB_H + so, brh + (lc0 + j) * 8, bsz);
            cpa16(sb + SB_L + so, brl + (lc0 + j) * 8, bsz);
        }
        cpa_commit_wait();
        __syncthreads();

        // ---- 4 k-steps of m16n8k16 ----
        #pragma unroll
        for (int ks = 0; ks < 4; ks++) {
            uint32_t ah[4][4], al[4][4], bh[4][2], bl[4][2];
            #pragma unroll
            for (int i = 0; i < 4; i++) {
                const int row = wm + i * 16 + (sub & 1) * 8 + l8;
                const int kb = ks * 32 + (sub >> 1) * 16;
                const uint32_t so = SWZ(row * 128 + kb);
                ldsm4(ah[i], sb + SA_H + so);
                ldsm4(al[i], sb + SA_L + so);
            }
            #pragma unroll
            for (int jp = 0; jp < 2; jp++) {
                const int row = wn + jp * 16 + (sub >> 1) * 8 + l8;
                const int kb = ks * 32 + (sub & 1) * 16;
                const uint32_t so = SWZ(row * 128 + kb);
                uint32_t t[4];
                ldsm4(t, sb + SB_H + so);
                bh[jp*2][0] = t[0]; bh[jp*2][1] = t[1];
                bh[jp*2+1][0] = t[2]; bh[jp*2+1][1] = t[3];
                ldsm4(t, sb + SB_L + so);
                bl[jp*2][0] = t[0]; bl[jp*2][1] = t[1];
                bl[jp*2+1][0] = t[2]; bl[jp*2+1][1] = t[3];
            }
            #pragma unroll
            for (int i = 0; i < 4; i++)
                #pragma unroll
                for (int j = 0; j < 4; j++) {
                    mma16816(acc[i][j], ah[i], bh[j]);
                    mma16816(acc[i][j], ah[i], bl[j]);
                    mma16816(acc[i][j], al[i], bh[j]);
                }
        }
        __syncthreads();
    }

    // ---- epilogue ----
    const int gm = lane >> 2;
    const int gn = (lane & 3) * 2;
    #pragma unroll
    for (int i = 0; i < 4; i++) {
        #pragma unroll
        for (int j = 0; j < 4; j++) {
            const int m = m0 + wm + i * 16 + gm;
            const int n = n0 + wn + j * 8 + gn;
            if (n < N) {
                *(float2*)(C + (long long)m * ldc + n) =
                    make_float2(acc[i][j][0], acc[i][j][1]);
                *(float2*)(C + (long long)(m + 8) * ldc + n) =
                    make_float2(acc[i][j][2], acc[i][j][3]);
            }
        }
    }
}

// ---------------- elementwise kernels ----------------
__global__ void split_kernel(const float* __restrict__ in,
                             bf16* __restrict__ hi, bf16* __restrict__ lo, long long n4)
{
    const long long i = (long long)blockIdx.x * blockDim.x + threadIdx.x;
    if (i >= n4) return;
    float4 v = *(const float4*)(in + i * 4);
    float f[4] = {v.x, v.y, v.z, v.w};
    __align__(8) bf16 h[4], l[4];
    #pragma unroll
    for (int j = 0; j < 4; j++) split2(f[j], h[j], l[j]);
    *(uint2*)(hi + i * 4) = *(uint2*)h;
    *(uint2*)(lo + i * 4) = *(uint2*)l;
}

__global__ void rmsnorm_split_kernel(const float* __restrict__ in,
                                     const float* __restrict__ w,
                                     bf16* __restrict__ hi, bf16* __restrict__ lo,
                                     int C, int ldin)
{
    const int row = blockIdx.x;
    const float* x = in + (long long)row * ldin;
    __shared__ float red[256];
    float s = 0.f;
    for (int c = threadIdx.x; c < C; c += 256) { float v = x[c]; s += v * v; }
    red[threadIdx.x] = s;
    __syncthreads();
    for (int st = 128; st > 0; st >>= 1) {
        if (threadIdx.x < st) red[threadIdx.x] += red[threadIdx.x + st];
        __syncthreads();
    }
    const float scale = rsqrtf(red[0] / (float)C + 1e-6f);
    for (int c = threadIdx.x; c < C; c += 256) {
        bf16 h, l;
        split2(x[c] * scale * w[c], h, l);
        hi[(long long)row * C + c] = h;
        lo[(long long)row * C + c] = l;
    }
}

__global__ void rope_q_kernel(float* __restrict__ q, const float* __restrict__ freqs)
{
    const int total = T_SEQ * NH * (ROPED / 2);
    int idx = blockIdx.x * blockDim.x + threadIdx.x;
    if (idx >= total) return;
    const int i = idx % (ROPED / 2);
    const int h = (idx / (ROPED / 2)) % NH;
    const int t = idx / (NH * (ROPED / 2));
    const double f = (double)freqs[t * (ROPED / 2) + i];
    const float c = (float)cos(f);
    const float s = (float)sin(f);
    float* p = q + (long long)t * (NH * QKD) + h * QKD + NOPE + 2 * i;
    const float x1 = p[0], x2 = p[1];
    p[0] = x1 * c - x2 * s;
    p[1] = x1 * s + x2 * c;
}

__global__ void rope_kpe_kernel(const float* __restrict__ kvfull,
                                const float* __restrict__ freqs,
                                float* __restrict__ kpe)
{
    const int total = T_SEQ * (ROPED / 2);
    int idx = blockIdx.x * blockDim.x + threadIdx.x;
    if (idx >= total) return;
    const int i = idx % (ROPED / 2);
    const int t = idx / (ROPED / 2);
    const double f = (double)freqs[t * (ROPED / 2) + i];
    const float c = (float)cos(f);
    const float s = (float)sin(f);
    const float* p = kvfull + (long long)t * KVAW + KVLORA + 2 * i;
    const float x1 = p[0], x2 = p[1];
    kpe[t * ROPED + 2 * i]     = x1 * c - x2 * s;
    kpe[t * ROPED + 2 * i + 1] = x1 * s + x2 * c;
}

__global__ void build_kh_split_kernel(const float* __restrict__ kv,
                                      const float* __restrict__ kpe,
                                      bf16* __restrict__ khh, bf16* __restrict__ khl)
{
    const int total = T_SEQ * NH * QKD;
    int idx = blockIdx.x * blockDim.x + threadIdx.x;
    if (idx >= total) return;
    const int d = idx % QKD;
    const int h = (idx / QKD) % NH;
    const int t = idx / (NH * QKD);
    float v;
    if (d < NOPE)
        v = kv[(long long)t * (NH * (NOPE + VD)) + h * (NOPE + VD) + d];
    else
        v = kpe[t * ROPED + (d - NOPE)];
    bf16 hh, ll;
    split2(v, hh, ll);
    khh[idx] = hh;
    khl[idx] = ll;
}

__global__ void vsplit_kernel(const float* __restrict__ kv,
                              bf16* __restrict__ vth, bf16* __restrict__ vtl)
{
    const int total = NH * VD * T_SEQ;
    int idx = blockIdx.x * blockDim.x + threadIdx.x;
    if (idx >= total) return;
    const int t = idx % T_SEQ;
    const int d = (idx / T_SEQ) % VD;
    const int h = idx / (T_SEQ * VD);
    const float v = kv[(long long)t * (NH * (NOPE + VD)) + h * (NOPE + VD) + NOPE + d];
    bf16 hh, ll;
    split2(v, hh, ll);
    vth[idx] = hh;
    vtl[idx] = ll;
}

__global__ void softmax_split_kernel(const float* __restrict__ scores,
                                     bf16* __restrict__ ph, bf16* __restrict__ pl)
{
    const int s = blockIdx.x;
    const int h = blockIdx.y;
    const float* row = scores + ((long long)h * T_SEQ + s) * T_SEQ;
    bf16* prh = ph + ((long long)h * T_SEQ + s) * T_SEQ;
    bf16* prl = pl + ((long long)h * T_SEQ + s) * T_SEQ;
    const float scale = (float)QKD * -0.5f;   // -96, matches reference literally
    const int n = s + 1;
    __shared__ float sv[T_SEQ];
    __shared__ float red[256];

    float m = -INFINITY;
    for (int t = threadIdx.x; t < n; t += 256) {
        const float f = row[t] * scale;
        sv[t] = f;
        m = fmaxf(m, f);
    }
    red[threadIdx.x] = m;
    __syncthreads();
    for (int st = 128; st > 0; st >>= 1) {
        if (threadIdx.x < st) red[threadIdx.x] = fmaxf(red[threadIdx.x], red[threadIdx.x + st]);
        __syncthreads();
    }
    m = red[0];
    __syncthreads();

    float sum = 0.f;
    for (int t = threadIdx.x; t < n; t += 256) {
        const float e = expf(sv[t] - m);
        sv[t] = e;
        sum += e;
    }
    red[threadIdx.x] = sum;
    __syncthreads();
    for (int st = 128; st > 0; st >>= 1) {
        if (threadIdx.x < st) red[threadIdx.x] += red[threadIdx.x + st];
        __syncthreads();
    }
    const float inv = 1.0f / red[0];

    for (int t = threadIdx.x; t < n; t += 256) {
        bf16 hh, ll;
        split2(sv[t] * inv, hh, ll);
        prh[t] = hh;
        prl[t] = ll;
    }
    const int zend = min(T_SEQ, ((s >> 7) + 1) << 7);
    const bf16 z0 = __float2bfloat16(0.f);
    for (int t = n + threadIdx.x; t < zend; t += 256) {
        prh[t] = z0;
        prl[t] = z0;
    }
}

// ---------------- launch ----------------
extern "C" void kernel_launch(void* const* d_in, const int* in_sizes, int n_in,
                              void* d_out, int out_size)
{
    (void)in_sizes; (void)n_in; (void)out_size;
    const float* x        = (const float*)d_in[0];
    const float* freqs    = (const float*)d_in[1];
    // d_in[2] = mask (causality applied analytically)
    const float* wq_a     = (const float*)d_in[3];
    const float* q_norm_w = (const float*)d_in[4];
    const float* wq_b     = (const float*)d_in[5];
    const float* wkv_a    = (const float*)d_in[6];
    const float* kv_norm_w= (const float*)d_in[7];
    const float* wkv_b    = (const float*)d_in[8];
    const float* wo       = (const float*)d_in[9];
    float* out = (float*)d_out;

    cudaFuncSetAttribute(bfgemm_kernel<0>, cudaFuncAttributeMaxDynamicSharedMemorySize, GSMEM);
    cudaFuncSetAttribute(bfgemm_kernel<1>, cudaFuncAttributeMaxDynamicSharedMemorySize, GSMEM);
    cudaFuncSetAttribute(bfgemm_kernel<2>, cudaFuncAttributeMaxDynamicSharedMemorySize, GSMEM);

    bf16 *xh, *xl, *wqah, *wqal, *wkvah, *wkval, *wqbh, *wqbl, *wkvbh, *wkvbl, *woh, *wol;
    bf16 *qanh, *qanl, *kvnh, *kvnl, *qh, *ql, *khh, *khl, *vth, *vtl, *pph, *ppl, *yh, *yl;
    float *qa, *kvfull, *qf, *kvf, *kpe, *scores, *y;
    cudaGetSymbolAddress((void**)&xh, g_xh);       cudaGetSymbolAddress((void**)&xl, g_xl);
    cudaGetSymbolAddress((void**)&wqah, g_wqa_h);  cudaGetSymbolAddress((void**)&wqal, g_wqa_l);
    cudaGetSymbolAddress((void**)&wkvah, g_wkva_h);cudaGetSymbolAddress((void**)&wkval, g_wkva_l);
    cudaGetSymbolAddress((void**)&wqbh, g_wqb_h);  cudaGetSymbolAddress((void**)&wqbl, g_wqb_l);
    cudaGetSymbolAddress((void**)&wkvbh, g_wkvb_h);cudaGetSymbolAddress((void**)&wkvbl, g_wkvb_l);
    cudaGetSymbolAddress((void**)&woh, g_wo_h);    cudaGetSymbolAddress((void**)&wol, g_wo_l);
    cudaGetSymbolAddress((void**)&qanh, g_qan_h);  cudaGetSymbolAddress((void**)&qanl, g_qan_l);
    cudaGetSymbolAddress((void**)&kvnh, g_kvn_h);  cudaGetSymbolAddress((void**)&kvnl, g_kvn_l);
    cudaGetSymbolAddress((void**)&qh, g_q_h);      cudaGetSymbolAddress((void**)&ql, g_q_l);
    cudaGetSymbolAddress((void**)&khh, g_kh_h);    cudaGetSymbolAddress((void**)&khl, g_kh_l);
    cudaGetSymbolAddress((void**)&vth, g_vt_h);    cudaGetSymbolAddress((void**)&vtl, g_vt_l);
    cudaGetSymbolAddress((void**)&pph, g_p_h);     cudaGetSymbolAddress((void**)&ppl, g_p_l);
    cudaGetSymbolAddress((void**)&yh, g_y_h);      cudaGetSymbolAddress((void**)&yl, g_y_l);
    cudaGetSymbolAddress((void**)&qa, g_qa);       cudaGetSymbolAddress((void**)&kvfull, g_kvfull);
    cudaGetSymbolAddress((void**)&qf, g_q);        cudaGetSymbolAddress((void**)&kvf, g_kv);
    cudaGetSymbolAddress((void**)&kpe, g_kpe);     cudaGetSymbolAddress((void**)&scores, g_scores);
    cudaGetSymbolAddress((void**)&y, g_y);

    const int TPB = 256;
    auto nblk = [](long long n) { return (int)((n + 255) / 256); };

    // ---- splits of inputs/weights ----
    split_kernel<<<nblk((long long)T_SEQ*DIM/4), TPB>>>(x, xh, xl, (long long)T_SEQ*DIM/4);
    split_kernel<<<nblk((long long)QLORA*DIM/4), TPB>>>(wq_a, wqah, wqal, (long long)QLORA*DIM/4);
    split_kernel<<<nblk((long long)KVAW*DIM/4), TPB>>>(wkv_a, wkvah, wkval, (long long)KVAW*DIM/4);
    split_kernel<<<nblk((long long)NH*QKD*QLORA/4), TPB>>>(wq_b, wqbh, wqbl, (long long)NH*QKD*QLORA/4);
    split_kernel<<<nblk((long long)NH*(NOPE+VD)*KVLORA/4), TPB>>>(wkv_b, wkvbh, wkvbl, (long long)NH*(NOPE+VD)*KVLORA/4);
    split_kernel<<<nblk((long long)DIM*NH*VD/4), TPB>>>(wo, woh, wol, (long long)DIM*NH*VD/4);

    // ---- qa = x @ wq_a^T ; kvfull = x @ wkv_a^T ----
    bfgemm_kernel<0><<<dim3(6, 16, 1), 256, GSMEM>>>(xh, xl, wqah, wqal, qa,
        T_SEQ, QLORA, DIM, DIM, DIM, QLORA, 0, 0, 0);
    bfgemm_kernel<0><<<dim3(5, 16, 1), 256, GSMEM>>>(xh, xl, wkvah, wkval, kvfull,
        T_SEQ, KVAW, DIM, DIM, DIM, KVAW, 0, 0, 0);

    // ---- rmsnorms (emit bf16 splits directly) ----
    rmsnorm_split_kernel<<<T_SEQ, TPB>>>(qa, q_norm_w, qanh, qanl, QLORA, QLORA);
    rmsnorm_split_kernel<<<T_SEQ, TPB>>>(kvfull, kv_norm_w, kvnh, kvnl, KVLORA, KVAW);

    // ---- q = qa_n @ wq_b^T ; rope ; split ----
    bfgemm_kernel<0><<<dim3(24, 16, 1), 256, GSMEM>>>(qanh, qanl, wqbh, wqbl, qf,
        T_SEQ, NH*QKD, QLORA, QLORA, QLORA, NH*QKD, 0, 0, 0);
    rope_q_kernel<<<nblk(T_SEQ*NH*(ROPED/2)), TPB>>>(qf, freqs);
    split_kernel<<<nblk((long long)T_SEQ*NH*QKD/4), TPB>>>(qf, qh, ql, (long long)T_SEQ*NH*QKD/4);

    // ---- kv = kv_n @ wkv_b^T ----
    bfgemm_kernel<0><<<dim3(32, 16, 1), 256, GSMEM>>>(kvnh, kvnl, wkvbh, wkvbl, kvf,
        T_SEQ, NH*(NOPE+VD), KVLORA, KVLORA, KVLORA, NH*(NOPE+VD), 0, 0, 0);

    // ---- kh / v preparation ----
    rope_kpe_kernel<<<nblk(T_SEQ*(ROPED/2)), TPB>>>(kvfull, freqs, kpe);
    build_kh_split_kernel<<<nblk((long long)T_SEQ*NH*QKD), TPB>>>(kvf, kpe, khh, khl);
    vsplit_kernel<<<nblk((long long)NH*VD*T_SEQ), TPB>>>(kvf, vth, vtl);

    // ---- scores = Q @ K^T (batched per head, causal tile skip) ----
    bfgemm_kernel<1><<<dim3(16, 16, NH), 256, GSMEM>>>(qh, ql, khh, khl, scores,
        T_SEQ, T_SEQ, QKD, NH*QKD, NH*QKD, T_SEQ,
        (long long)QKD, (long long)QKD, (long long)T_SEQ*T_SEQ);

    // ---- softmax + hi/lo split of P ----
    softmax_split_kernel<<<dim3(T_SEQ, NH), TPB>>>(scores, pph, ppl);

    // ---- y = P @ V (batched per head, causal K-limit) ----
    bfgemm_kernel<2><<<dim3(1, 16, NH), 256, GSMEM>>>(pph, ppl, vth, vtl, y,
        T_SEQ, VD, T_SEQ, T_SEQ, T_SEQ, NH*VD,
        (long long)T_SEQ*T_SEQ, (long long)VD*T_SEQ, (long long)VD);
    split_kernel<<<nblk((long long)T_SEQ*NH*VD/4), TPB>>>(y, yh, yl, (long long)T_SEQ*NH*VD/4);

    // ---- out = y @ wo^T ----
    bfgemm_kernel<0><<<dim3(16, 16, 1), 256, GSMEM>>>(yh, yl, woh, wol, out,
        T_SEQ, DIM, NH*VD, NH*VD, NH*VD, DIM, 0, 0, 0);
}